// round 1
// baseline (speedup 1.0000x reference)
#include <cuda_runtime.h>
#include <math.h>

#define BSZ 8
#define SEQ 1024
#define EMB 1024
#define NH 16
#define HD 64
#define M_TOT (BSZ*SEQ)   // 8192

// Scratch (no cudaMalloc allowed): projected Q/K/V and attention context.
__device__ float g_Q[(size_t)BSZ*SEQ*EMB];
__device__ float g_K[(size_t)BSZ*SEQ*EMB];
__device__ float g_V[(size_t)BSZ*SEQ*EMB];
__device__ float g_C[(size_t)BSZ*SEQ*EMB];

// ---------------------------------------------------------------------------
// C[M,N] = scale * (A[M,K] @ W[N,K]^T + bias[N])    M=8192, N=K=1024
// 128x128 block tile, BK=16, 256 threads, 8x8 per-thread tile.
// ---------------------------------------------------------------------------
__global__ __launch_bounds__(256) void sgemm_nt_bias(
    const float* __restrict__ A, const float* __restrict__ W,
    const float* __restrict__ bias, float* __restrict__ C, float scale)
{
    const int K = EMB, N = EMB;
    __shared__ float As[16][132];   // [k][m], pad 132 keeps 16B row alignment
    __shared__ float Bs[16][132];   // [k][n]

    const int tid = threadIdx.x;
    const int tx = tid & 15;        // col group
    const int ty = tid >> 4;        // row group
    const int bx = blockIdx.x * 128;
    const int by = blockIdx.y * 128;

    float acc[8][8];
#pragma unroll
    for (int i = 0; i < 8; i++)
#pragma unroll
        for (int j = 0; j < 8; j++) acc[i][j] = 0.f;

    const float* Ab = A + (size_t)by * K;
    const float* Wb = W + (size_t)bx * K;

    for (int k0 = 0; k0 < K; k0 += 16) {
#pragma unroll
        for (int s2 = 0; s2 < 2; s2++) {
            int slot = tid + s2 * 256;          // 0..511
            int r  = slot >> 2;                 // 0..127
            int c4 = (slot & 3) << 2;           // 0,4,8,12
            float4 av = *(const float4*)(Ab + (size_t)r * K + k0 + c4);
            As[c4+0][r] = av.x; As[c4+1][r] = av.y;
            As[c4+2][r] = av.z; As[c4+3][r] = av.w;
            float4 bv = *(const float4*)(Wb + (size_t)r * K + k0 + c4);
            Bs[c4+0][r] = bv.x; Bs[c4+1][r] = bv.y;
            Bs[c4+2][r] = bv.z; Bs[c4+3][r] = bv.w;
        }
        __syncthreads();
#pragma unroll
        for (int k = 0; k < 16; k++) {
            float ar[8], br[8];
#pragma unroll
            for (int i = 0; i < 8; i++) ar[i] = As[k][ty*8 + i];
#pragma unroll
            for (int j = 0; j < 8; j++) br[j] = Bs[k][tx + 16*j];
#pragma unroll
            for (int i = 0; i < 8; i++)
#pragma unroll
                for (int j = 0; j < 8; j++)
                    acc[i][j] = fmaf(ar[i], br[j], acc[i][j]);
        }
        __syncthreads();
    }

#pragma unroll
    for (int j = 0; j < 8; j++) {
        int n = bx + tx + 16*j;
        float bv = __ldg(&bias[n]);
#pragma unroll
        for (int i = 0; i < 8; i++) {
            int m = by + ty*8 + i;
            C[(size_t)m * N + n] = (acc[i][j] + bv) * scale;
        }
    }
}

// ---------------------------------------------------------------------------
// Fused flash-style attention for one (b, h, 64-row query block).
// Q/K/V/out layout: [b, s, h, d] (i.e. projected [b,s,E] with E = h*64+d).
// Online softmax over 16 key blocks of 64.
// 256 threads: tx = t&15 (col group), ty = t>>4 (row group), 4x4 per thread.
// ---------------------------------------------------------------------------
__global__ __launch_bounds__(256) void attn_kernel(
    const float* __restrict__ Qg, const float* __restrict__ Kg,
    const float* __restrict__ Vg, float* __restrict__ Og)
{
    extern __shared__ float sm[];
    float (*Qs)[68]  = (float (*)[68])(sm);             // [row][d]
    float (*KsT)[68] = (float (*)[68])(sm + 64*68);     // [d][col]  (transposed K)
    float (*Vs)[68]  = (float (*)[68])(sm + 2*64*68);   // [s][d]
    float (*Ps)[68]  = (float (*)[68])(sm + 3*64*68);   // [row][s]

    const int t  = threadIdx.x;
    const int tx = t & 15, ty = t >> 4;
    const int w  = t >> 5, l = t & 31;
    const int b = blockIdx.z, h = blockIdx.y;
    const int q0 = blockIdx.x * 64;

    // global row s base: ((b*SEQ + s)*NH + h)*HD ; row stride = NH*HD = 1024
    const size_t bh = ((size_t)b * SEQ * NH + h) * HD;

    // ---- load Q tile (64x64) ----
#pragma unroll
    for (int s2 = 0; s2 < 4; s2++) {
        int slot = t + s2 * 256;
        int r = slot >> 4, c4 = (slot & 15) << 2;
        *(float4*)&Qs[r][c4] =
            *(const float4*)(Qg + bh + (size_t)(q0 + r) * 1024 + c4);
    }

    float m_i[4], l_i[4], acc[4][4];
#pragma unroll
    for (int i = 0; i < 4; i++) {
        m_i[i] = -1e30f; l_i[i] = 0.f;
#pragma unroll
        for (int j = 0; j < 4; j++) acc[i][j] = 0.f;
    }

    for (int kb = 0; kb < SEQ/64; kb++) {
        const int k0 = kb * 64;
        __syncthreads();   // all consumers of previous K/V tiles done
        // K transposed: warp-coalesced gmem reads, strided smem stores
#pragma unroll
        for (int rr = 0; rr < 8; rr++) {
            int row = w*8 + rr;
            const float* kp = Kg + bh + (size_t)(k0 + row) * 1024;
            KsT[l     ][row] = kp[l];
            KsT[l + 32][row] = kp[l + 32];
        }
#pragma unroll
        for (int s2 = 0; s2 < 4; s2++) {
            int slot = t + s2 * 256;
            int r = slot >> 4, c4 = (slot & 15) << 2;
            *(float4*)&Vs[r][c4] =
                *(const float4*)(Vg + bh + (size_t)(k0 + r) * 1024 + c4);
        }
        __syncthreads();

        // ---- S = Q K^T (4x4 per thread) ----
        float sf[4][4];
#pragma unroll
        for (int i = 0; i < 4; i++)
#pragma unroll
            for (int j = 0; j < 4; j++) sf[i][j] = 0.f;

#pragma unroll
        for (int d4 = 0; d4 < 64; d4 += 4) {
            float q4[4][4];
#pragma unroll
            for (int i = 0; i < 4; i++) {
                float4 qv = *(const float4*)&Qs[ty*4 + i][d4];
                q4[i][0] = qv.x; q4[i][1] = qv.y; q4[i][2] = qv.z; q4[i][3] = qv.w;
            }
#pragma unroll
            for (int dd = 0; dd < 4; dd++) {
                float4 kv = *(const float4*)&KsT[d4 + dd][tx*4];
#pragma unroll
                for (int i = 0; i < 4; i++) {
                    sf[i][0] = fmaf(q4[i][dd], kv.x, sf[i][0]);
                    sf[i][1] = fmaf(q4[i][dd], kv.y, sf[i][1]);
                    sf[i][2] = fmaf(q4[i][dd], kv.z, sf[i][2]);
                    sf[i][3] = fmaf(q4[i][dd], kv.w, sf[i][3]);
                }
            }
        }

        // ---- online softmax (rows owned by 16-lane tx-groups) ----
#pragma unroll
        for (int i = 0; i < 4; i++) {
            float mx = fmaxf(fmaxf(sf[i][0], sf[i][1]), fmaxf(sf[i][2], sf[i][3]));
#pragma unroll
            for (int off = 8; off >= 1; off >>= 1)
                mx = fmaxf(mx, __shfl_xor_sync(0xffffffffu, mx, off));
            float m_new = fmaxf(m_i[i], mx);
            float corr  = __expf(m_i[i] - m_new);
            float p[4], ps = 0.f;
#pragma unroll
            for (int j = 0; j < 4; j++) { p[j] = __expf(sf[i][j] - m_new); ps += p[j]; }
#pragma unroll
            for (int off = 8; off >= 1; off >>= 1)
                ps += __shfl_xor_sync(0xffffffffu, ps, off);
            l_i[i] = l_i[i] * corr + ps;
            m_i[i] = m_new;
#pragma unroll
            for (int j = 0; j < 4; j++) {
                acc[i][j] *= corr;
                Ps[ty*4 + i][tx*4 + j] = p[j];
            }
        }
        __syncwarp();   // P rows are produced & consumed within one warp

        // ---- O += P @ V ----
#pragma unroll 8
        for (int s = 0; s < 64; s++) {
            float4 vv = *(const float4*)&Vs[s][tx*4];
#pragma unroll
            for (int i = 0; i < 4; i++) {
                float pp = Ps[ty*4 + i][s];
                acc[i][0] = fmaf(pp, vv.x, acc[i][0]);
                acc[i][1] = fmaf(pp, vv.y, acc[i][1]);
                acc[i][2] = fmaf(pp, vv.z, acc[i][2]);
                acc[i][3] = fmaf(pp, vv.w, acc[i][3]);
            }
        }
    }

    // ---- epilogue: normalize and store context ([b,s,h,d] == [b,t,E]) ----
#pragma unroll
    for (int i = 0; i < 4; i++) {
        float inv = 1.0f / l_i[i];
        float4 o;
        o.x = acc[i][0] * inv; o.y = acc[i][1] * inv;
        o.z = acc[i][2] * inv; o.w = acc[i][3] * inv;
        *(float4*)(Og + bh + (size_t)(q0 + ty*4 + i) * 1024 + tx*4) = o;
    }
}

// ---------------------------------------------------------------------------
extern "C" void kernel_launch(void* const* d_in, const int* in_sizes, int n_in,
                              void* d_out, int out_size)
{
    const float* q  = (const float*)d_in[0];
    const float* k  = (const float*)d_in[1];
    const float* v  = (const float*)d_in[2];
    const float* Wq = (const float*)d_in[3];
    const float* bq = (const float*)d_in[4];
    const float* Wk = (const float*)d_in[5];
    const float* bk = (const float*)d_in[6];
    const float* Wv = (const float*)d_in[7];
    const float* bv = (const float*)d_in[8];
    const float* Wo = (const float*)d_in[9];
    const float* bo = (const float*)d_in[10];
    float* out = (float*)d_out;

    float *gQ, *gK, *gV, *gC;
    cudaGetSymbolAddress((void**)&gQ, g_Q);
    cudaGetSymbolAddress((void**)&gK, g_K);
    cudaGetSymbolAddress((void**)&gV, g_V);
    cudaGetSymbolAddress((void**)&gC, g_C);

    const float scaling = 0.125f;   // HD^-0.5 = 64^-0.5

    dim3 gg(EMB/128, M_TOT/128);    // (8, 64)
    sgemm_nt_bias<<<gg, 256>>>(q, Wq, bq, gQ, scaling);
    sgemm_nt_bias<<<gg, 256>>>(k, Wk, bk, gK, 1.0f);
    sgemm_nt_bias<<<gg, 256>>>(v, Wv, bv, gV, 1.0f);

    size_t smem = 4 * 64 * 68 * sizeof(float);   // 69632 B
    cudaFuncSetAttribute(attn_kernel,
                         cudaFuncAttributeMaxDynamicSharedMemorySize, (int)smem);
    attn_kernel<<<dim3(SEQ/64, NH, BSZ), 256, smem>>>(gQ, gK, gV, gC);

    sgemm_nt_bias<<<gg, 256>>>(gC, Wo, bo, out, 1.0f);
}

// round 3
// speedup vs baseline: 1.7174x; 1.7174x over previous
#include <cuda_runtime.h>
#include <cuda_bf16.h>
#include <cstdint>
#include <math.h>

#define BSZ 8
#define SEQ 1024
#define EMB 1024
#define NH 16
#define HD 64
#define M_TOT (BSZ*SEQ)   // 8192

// ---------------- scratch (__device__ globals; no allocation allowed) -------
__device__ float g_Q[(size_t)M_TOT*EMB];
__device__ float g_K[(size_t)M_TOT*EMB];
__device__ float g_V[(size_t)M_TOT*EMB];
__device__ float g_C[(size_t)M_TOT*EMB];
__device__ __nv_bfloat16 g_in_hi[(size_t)M_TOT*EMB];
__device__ __nv_bfloat16 g_in_lo[(size_t)M_TOT*EMB];
__device__ __nv_bfloat16 g_w_hi[(size_t)EMB*EMB];
__device__ __nv_bfloat16 g_w_lo[(size_t)EMB*EMB];

__device__ __forceinline__ uint32_t smem_u32(const void* p) {
    uint32_t a;
    asm("{ .reg .u64 t; cvta.to.shared.u64 t, %1; cvt.u32.u64 %0, t; }"
        : "=r"(a) : "l"(p));
    return a;
}

__device__ __forceinline__ void mma16816(float* c, const uint32_t* a, const uint32_t* b) {
    asm volatile(
        "mma.sync.aligned.m16n8k16.row.col.f32.bf16.bf16.f32 "
        "{%0,%1,%2,%3}, {%4,%5,%6,%7}, {%8,%9}, {%0,%1,%2,%3};"
        : "+f"(c[0]), "+f"(c[1]), "+f"(c[2]), "+f"(c[3])
        : "r"(a[0]), "r"(a[1]), "r"(a[2]), "r"(a[3]), "r"(b[0]), "r"(b[1]));
}

// ---------------- fp32 -> bf16 hi/lo split ----------------------------------
__global__ __launch_bounds__(256) void split_bf16(
    const float4* __restrict__ x, uint2* __restrict__ hi, uint2* __restrict__ lo, int n4)
{
    int i = blockIdx.x * 256 + threadIdx.x;
    if (i >= n4) return;
    float4 v = x[i];
    __nv_bfloat16 h0 = __float2bfloat16(v.x);
    __nv_bfloat16 h1 = __float2bfloat16(v.y);
    __nv_bfloat16 h2 = __float2bfloat16(v.z);
    __nv_bfloat16 h3 = __float2bfloat16(v.w);
    __nv_bfloat16 l0 = __float2bfloat16(v.x - __bfloat162float(h0));
    __nv_bfloat16 l1 = __float2bfloat16(v.y - __bfloat162float(h1));
    __nv_bfloat16 l2 = __float2bfloat16(v.z - __bfloat162float(h2));
    __nv_bfloat16 l3 = __float2bfloat16(v.w - __bfloat162float(h3));
    __nv_bfloat162 ha = {h0, h1}, hb = {h2, h3};
    __nv_bfloat162 la = {l0, l1}, lb = {l2, l3};
    uint2 ho, loo;
    ho.x = *reinterpret_cast<uint32_t*>(&ha); ho.y = *reinterpret_cast<uint32_t*>(&hb);
    loo.x = *reinterpret_cast<uint32_t*>(&la); loo.y = *reinterpret_cast<uint32_t*>(&lb);
    hi[i] = ho; lo[i] = loo;
}

// ---------------- mma.sync bf16-split GEMM ----------------------------------
// C[M,N] = scale * (A[M,K] @ W[N,K]^T + bias[N]); M=8192, N=K=1024.
// 128x128 CTA tile, BK=32, 8 warps (2x4), warp tile 64x32.
// Smem row stride 80B (== 16 mod 128 -> conflict-free ldmatrix).
#define BK 32
#define NCHUNK (EMB/BK)            // 32
#define ROW_B 80                   // bytes per smem row (64B payload + 16B pad)
#define TILE_BYT (128*ROW_B)       // 10240
#define STAGE_BYT (4*TILE_BYT)     // 40960
#define GEMM_SMEM (2*STAGE_BYT)    // 81920

__global__ __launch_bounds__(256) void gemm_mma(
    const __nv_bfloat16* __restrict__ Ahi, const __nv_bfloat16* __restrict__ Alo,
    const __nv_bfloat16* __restrict__ Bhi, const __nv_bfloat16* __restrict__ Blo,
    const float* __restrict__ bias, float* __restrict__ C, float scale)
{
    extern __shared__ char smc[];
    const int tid = threadIdx.x;
    const int lane = tid & 31, w = tid >> 5;
    const int wy = w >> 2, wx = w & 3;           // 2 x 4 warp grid
    const int bx = blockIdx.x * 128, by = blockIdx.y * 128;
    const uint32_t sbase = smem_u32(smc);

    const char* gsrc[4] = {
        (const char*)(Ahi + (size_t)by * EMB),
        (const char*)(Alo + (size_t)by * EMB),
        (const char*)(Bhi + (size_t)bx * EMB),
        (const char*)(Blo + (size_t)bx * EMB)};

    auto prefetch = [&](int kb, int st) {
#pragma unroll
        for (int t = 0; t < 4; t++)
#pragma unroll
            for (int s = 0; s < 2; s++) {
                int idx = tid + s * 256;         // 0..511
                int r = idx >> 2, c = idx & 3;   // 128 rows x 4 x 16B
                const char* src = gsrc[t] + ((size_t)r * EMB + (size_t)kb * BK) * 2 + c * 16;
                uint32_t dst = sbase + (uint32_t)st * STAGE_BYT + t * TILE_BYT
                             + (uint32_t)r * ROW_B + c * 16;
                asm volatile("cp.async.cg.shared.global [%0], [%1], 16;"
                             :: "r"(dst), "l"(src));
            }
        asm volatile("cp.async.commit_group;");
    };

    float acc[4][4][4];
#pragma unroll
    for (int mi = 0; mi < 4; mi++)
#pragma unroll
        for (int ni = 0; ni < 4; ni++)
#pragma unroll
            for (int j = 0; j < 4; j++) acc[mi][ni][j] = 0.f;

    prefetch(0, 0);

    for (int kb = 0; kb < NCHUNK; kb++) {
        if (kb + 1 < NCHUNK) {
            prefetch(kb + 1, (kb + 1) & 1);
            asm volatile("cp.async.wait_group 1;");
        } else {
            asm volatile("cp.async.wait_group 0;");
        }
        __syncthreads();
        const uint32_t st = sbase + (uint32_t)(kb & 1) * STAGE_BYT;

#pragma unroll
        for (int ks = 0; ks < 2; ks++) {
            // ---- B fragments (hi & lo) ----
            uint32_t bh[4][2], bl[4][2];
            const uint32_t brow = wx * 32 + (lane & 7);
            const uint32_t bcol = ks * 16 + ((lane >> 3) & 1) * 8;
#pragma unroll
            for (int ni = 0; ni < 4; ni++) {
                uint32_t ab = st + 2 * TILE_BYT + (brow + ni * 8) * ROW_B + bcol * 2;
                asm volatile("ldmatrix.sync.aligned.m8n8.x2.shared.b16 {%0,%1}, [%2];"
                             : "=r"(bh[ni][0]), "=r"(bh[ni][1]) : "r"(ab));
                uint32_t ab2 = ab + TILE_BYT;
                asm volatile("ldmatrix.sync.aligned.m8n8.x2.shared.b16 {%0,%1}, [%2];"
                             : "=r"(bl[ni][0]), "=r"(bl[ni][1]) : "r"(ab2));
            }
            // ---- A fragments per 16-row slab, 12 MMAs each ----
            const uint32_t arow = wy * 64 + (lane & 15);
            const uint32_t acol = ks * 16 + (lane >> 4) * 8;
#pragma unroll
            for (int mi = 0; mi < 4; mi++) {
                uint32_t ah[4], al[4];
                uint32_t aa = st + (arow + mi * 16) * ROW_B + acol * 2;
                asm volatile("ldmatrix.sync.aligned.m8n8.x4.shared.b16 {%0,%1,%2,%3}, [%4];"
                             : "=r"(ah[0]), "=r"(ah[1]), "=r"(ah[2]), "=r"(ah[3]) : "r"(aa));
                uint32_t aa2 = aa + TILE_BYT;
                asm volatile("ldmatrix.sync.aligned.m8n8.x4.shared.b16 {%0,%1,%2,%3}, [%4];"
                             : "=r"(al[0]), "=r"(al[1]), "=r"(al[2]), "=r"(al[3]) : "r"(aa2));
#pragma unroll
                for (int ni = 0; ni < 4; ni++) {
                    mma16816(acc[mi][ni], ah, bh[ni]);   // hi*hi
                    mma16816(acc[mi][ni], ah, bl[ni]);   // hi*lo
                    mma16816(acc[mi][ni], al, bh[ni]);   // lo*hi
                }
            }
        }
        __syncthreads();
    }

    // ---- epilogue: bias + scale, direct fp32 stores ----
    const int g = lane >> 2, tg = lane & 3;
#pragma unroll
    for (int mi = 0; mi < 4; mi++) {
        int row0 = by + wy * 64 + mi * 16 + g;
#pragma unroll
        for (int ni = 0; ni < 4; ni++) {
            int col = bx + wx * 32 + ni * 8 + tg * 2;
            float b0 = __ldg(bias + col), b1 = __ldg(bias + col + 1);
            float2 o0, o1;
            o0.x = (acc[mi][ni][0] + b0) * scale;
            o0.y = (acc[mi][ni][1] + b1) * scale;
            o1.x = (acc[mi][ni][2] + b0) * scale;
            o1.y = (acc[mi][ni][3] + b1) * scale;
            *(float2*)&C[(size_t)row0 * EMB + col] = o0;
            *(float2*)&C[(size_t)(row0 + 8) * EMB + col] = o1;
        }
    }
}

// ---------------- fused flash attention (fp32, as in R1) --------------------
__global__ __launch_bounds__(256) void attn_kernel(
    const float* __restrict__ Qg, const float* __restrict__ Kg,
    const float* __restrict__ Vg, float* __restrict__ Og)
{
    extern __shared__ float sm[];
    float (*Qs)[68]  = (float (*)[68])(sm);
    float (*KsT)[68] = (float (*)[68])(sm + 64*68);
    float (*Vs)[68]  = (float (*)[68])(sm + 2*64*68);
    float (*Ps)[68]  = (float (*)[68])(sm + 3*64*68);

    const int t  = threadIdx.x;
    const int tx = t & 15, ty = t >> 4;
    const int w  = t >> 5, l = t & 31;
    const int b = blockIdx.z, h = blockIdx.y;
    const int q0 = blockIdx.x * 64;
    const size_t bh = ((size_t)b * SEQ * NH + h) * HD;

#pragma unroll
    for (int s2 = 0; s2 < 4; s2++) {
        int slot = t + s2 * 256;
        int r = slot >> 4, c4 = (slot & 15) << 2;
        *(float4*)&Qs[r][c4] =
            *(const float4*)(Qg + bh + (size_t)(q0 + r) * 1024 + c4);
    }

    float m_i[4], l_i[4], acc[4][4];
#pragma unroll
    for (int i = 0; i < 4; i++) {
        m_i[i] = -1e30f; l_i[i] = 0.f;
#pragma unroll
        for (int j = 0; j < 4; j++) acc[i][j] = 0.f;
    }

    for (int kb = 0; kb < SEQ/64; kb++) {
        const int k0 = kb * 64;
        __syncthreads();
#pragma unroll
        for (int rr = 0; rr < 8; rr++) {
            int row = w*8 + rr;
            const float* kp = Kg + bh + (size_t)(k0 + row) * 1024;
            KsT[l     ][row] = kp[l];
            KsT[l + 32][row] = kp[l + 32];
        }
#pragma unroll
        for (int s2 = 0; s2 < 4; s2++) {
            int slot = t + s2 * 256;
            int r = slot >> 4, c4 = (slot & 15) << 2;
            *(float4*)&Vs[r][c4] =
                *(const float4*)(Vg + bh + (size_t)(k0 + r) * 1024 + c4);
        }
        __syncthreads();

        float sf[4][4];
#pragma unroll
        for (int i = 0; i < 4; i++)
#pragma unroll
            for (int j = 0; j < 4; j++) sf[i][j] = 0.f;

#pragma unroll
        for (int d4 = 0; d4 < 64; d4 += 4) {
            float q4[4][4];
#pragma unroll
            for (int i = 0; i < 4; i++) {
                float4 qv = *(const float4*)&Qs[ty*4 + i][d4];
                q4[i][0] = qv.x; q4[i][1] = qv.y; q4[i][2] = qv.z; q4[i][3] = qv.w;
            }
#pragma unroll
            for (int dd = 0; dd < 4; dd++) {
                float4 kv = *(const float4*)&KsT[d4 + dd][tx*4];
#pragma unroll
                for (int i = 0; i < 4; i++) {
                    sf[i][0] = fmaf(q4[i][dd], kv.x, sf[i][0]);
                    sf[i][1] = fmaf(q4[i][dd], kv.y, sf[i][1]);
                    sf[i][2] = fmaf(q4[i][dd], kv.z, sf[i][2]);
                    sf[i][3] = fmaf(q4[i][dd], kv.w, sf[i][3]);
                }
            }
        }

#pragma unroll
        for (int i = 0; i < 4; i++) {
            float mx = fmaxf(fmaxf(sf[i][0], sf[i][1]), fmaxf(sf[i][2], sf[i][3]));
#pragma unroll
            for (int off = 8; off >= 1; off >>= 1)
                mx = fmaxf(mx, __shfl_xor_sync(0xffffffffu, mx, off));
            float m_new = fmaxf(m_i[i], mx);
            float corr  = __expf(m_i[i] - m_new);
            float p[4], ps = 0.f;
#pragma unroll
            for (int j = 0; j < 4; j++) { p[j] = __expf(sf[i][j] - m_new); ps += p[j]; }
#pragma unroll
            for (int off = 8; off >= 1; off >>= 1)
                ps += __shfl_xor_sync(0xffffffffu, ps, off);
            l_i[i] = l_i[i] * corr + ps;
            m_i[i] = m_new;
#pragma unroll
            for (int j = 0; j < 4; j++) {
                acc[i][j] *= corr;
                Ps[ty*4 + i][tx*4 + j] = p[j];
            }
        }
        __syncwarp();

#pragma unroll 8
        for (int s = 0; s < 64; s++) {
            float4 vv = *(const float4*)&Vs[s][tx*4];
#pragma unroll
            for (int i = 0; i < 4; i++) {
                float pp = Ps[ty*4 + i][s];
                acc[i][0] = fmaf(pp, vv.x, acc[i][0]);
                acc[i][1] = fmaf(pp, vv.y, acc[i][1]);
                acc[i][2] = fmaf(pp, vv.z, acc[i][2]);
                acc[i][3] = fmaf(pp, vv.w, acc[i][3]);
            }
        }
    }

#pragma unroll
    for (int i = 0; i < 4; i++) {
        float inv = 1.0f / l_i[i];
        float4 o;
        o.x = acc[i][0] * inv; o.y = acc[i][1] * inv;
        o.z = acc[i][2] * inv; o.w = acc[i][3] * inv;
        *(float4*)(Og + bh + (size_t)(q0 + ty*4 + i) * 1024 + tx*4) = o;
    }
}

// ---------------------------------------------------------------------------
extern "C" void kernel_launch(void* const* d_in, const int* in_sizes, int n_in,
                              void* d_out, int out_size)
{
    const float* q  = (const float*)d_in[0];
    const float* k  = (const float*)d_in[1];
    const float* v  = (const float*)d_in[2];
    const float* Wq = (const float*)d_in[3];
    const float* bq = (const float*)d_in[4];
    const float* Wk = (const float*)d_in[5];
    const float* bk = (const float*)d_in[6];
    const float* Wv = (const float*)d_in[7];
    const float* bv = (const float*)d_in[8];
    const float* Wo = (const float*)d_in[9];
    const float* bo = (const float*)d_in[10];
    float* out = (float*)d_out;

    float *gQ, *gK, *gV, *gC;
    __nv_bfloat16 *inh, *inl, *wh, *wl;
    cudaGetSymbolAddress((void**)&gQ, g_Q);
    cudaGetSymbolAddress((void**)&gK, g_K);
    cudaGetSymbolAddress((void**)&gV, g_V);
    cudaGetSymbolAddress((void**)&gC, g_C);
    cudaGetSymbolAddress((void**)&inh, g_in_hi);
    cudaGetSymbolAddress((void**)&inl, g_in_lo);
    cudaGetSymbolAddress((void**)&wh, g_w_hi);
    cudaGetSymbolAddress((void**)&wl, g_w_lo);

    const int attn_smem = 4 * 64 * 68 * sizeof(float);   // 69632
    cudaFuncSetAttribute(gemm_mma,
        cudaFuncAttributeMaxDynamicSharedMemorySize, GEMM_SMEM);
    cudaFuncSetAttribute(attn_kernel,
        cudaFuncAttributeMaxDynamicSharedMemorySize, attn_smem);

    const int n4_in = M_TOT * EMB / 4;
    const int n4_w  = EMB * EMB / 4;
    dim3 gg(EMB / 128, M_TOT / 128);     // (8, 64)
    const float scaling = 0.125f;        // 64^-0.5

    // Q projection
    split_bf16<<<n4_in/256, 256>>>((const float4*)q, (uint2*)inh, (uint2*)inl, n4_in);
    split_bf16<<<n4_w /256, 256>>>((const float4*)Wq, (uint2*)wh, (uint2*)wl, n4_w);
    gemm_mma<<<gg, 256, GEMM_SMEM>>>(inh, inl, wh, wl, bq, gQ, scaling);
    // K projection
    split_bf16<<<n4_in/256, 256>>>((const float4*)k, (uint2*)inh, (uint2*)inl, n4_in);
    split_bf16<<<n4_w /256, 256>>>((const float4*)Wk, (uint2*)wh, (uint2*)wl, n4_w);
    gemm_mma<<<gg, 256, GEMM_SMEM>>>(inh, inl, wh, wl, bk, gK, 1.0f);
    // V projection
    split_bf16<<<n4_in/256, 256>>>((const float4*)v, (uint2*)inh, (uint2*)inl, n4_in);
    split_bf16<<<n4_w /256, 256>>>((const float4*)Wv, (uint2*)wh, (uint2*)wl, n4_w);
    gemm_mma<<<gg, 256, GEMM_SMEM>>>(inh, inl, wh, wl, bv, gV, 1.0f);
    // attention
    attn_kernel<<<dim3(SEQ/64, NH, BSZ), 256, attn_smem>>>(gQ, gK, gV, gC);
    // output projection
    split_bf16<<<n4_in/256, 256>>>((const float4*)gC, (uint2*)inh, (uint2*)inl, n4_in);
    split_bf16<<<n4_w /256, 256>>>((const float4*)Wo, (uint2*)wh, (uint2*)wl, n4_w);
    gemm_mma<<<gg, 256, GEMM_SMEM>>>(inh, inl, wh, wl, bo, out, 1.0f);
}

// round 5
// speedup vs baseline: 2.5887x; 1.5073x over previous
#include <cuda_runtime.h>
#include <cuda_bf16.h>
#include <cstdint>
#include <math.h>

#define BSZ 8
#define SEQ 1024
#define EMB 1024
#define NH 16
#define HD 64
#define M_TOT (BSZ*SEQ)   // 8192

// ---------------- scratch (__device__ globals; no allocation allowed) -------
__device__ __nv_bfloat16 g_Qh[(size_t)M_TOT*EMB];
__device__ __nv_bfloat16 g_Ql[(size_t)M_TOT*EMB];
__device__ __nv_bfloat16 g_Kh[(size_t)M_TOT*EMB];
__device__ __nv_bfloat16 g_Kl[(size_t)M_TOT*EMB];
__device__ __nv_bfloat16 g_Vh[(size_t)M_TOT*EMB];
__device__ __nv_bfloat16 g_Vl[(size_t)M_TOT*EMB];
__device__ __nv_bfloat16 g_Ch[(size_t)M_TOT*EMB];
__device__ __nv_bfloat16 g_Cl[(size_t)M_TOT*EMB];
__device__ __nv_bfloat16 g_in_hi[(size_t)M_TOT*EMB];
__device__ __nv_bfloat16 g_in_lo[(size_t)M_TOT*EMB];
__device__ __nv_bfloat16 g_w_hi[(size_t)EMB*EMB];
__device__ __nv_bfloat16 g_w_lo[(size_t)EMB*EMB];

__device__ __forceinline__ uint32_t smem_u32(const void* p) {
    uint32_t a;
    asm("{ .reg .u64 t; cvta.to.shared.u64 t, %1; cvt.u32.u64 %0, t; }"
        : "=r"(a) : "l"(p));
    return a;
}

__device__ __forceinline__ void mma16816(float* c, const uint32_t* a, const uint32_t* b) {
    asm volatile(
        "mma.sync.aligned.m16n8k16.row.col.f32.bf16.bf16.f32 "
        "{%0,%1,%2,%3}, {%4,%5,%6,%7}, {%8,%9}, {%0,%1,%2,%3};"
        : "+f"(c[0]), "+f"(c[1]), "+f"(c[2]), "+f"(c[3])
        : "r"(a[0]), "r"(a[1]), "r"(a[2]), "r"(a[3]), "r"(b[0]), "r"(b[1]));
}

// split pair (x,y) into hi/lo packed bf16x2
__device__ __forceinline__ void split2(float x, float y, uint32_t& hi, uint32_t& lo) {
    __nv_bfloat16 hx = __float2bfloat16(x), hy = __float2bfloat16(y);
    float rx = x - __bfloat162float(hx), ry = y - __bfloat162float(hy);
    __nv_bfloat162 hp = {hx, hy};
    __nv_bfloat162 lp = {__float2bfloat16(rx), __float2bfloat16(ry)};
    hi = *reinterpret_cast<uint32_t*>(&hp);
    lo = *reinterpret_cast<uint32_t*>(&lp);
}

// ---------------- fp32 -> bf16 hi/lo split (inputs & weights) ---------------
__global__ __launch_bounds__(256) void split_bf16(
    const float4* __restrict__ x, uint2* __restrict__ hi, uint2* __restrict__ lo, int n4)
{
    int i = blockIdx.x * 256 + threadIdx.x;
    if (i >= n4) return;
    float4 v = x[i];
    uint32_t h0, l0, h1, l1;
    split2(v.x, v.y, h0, l0);
    split2(v.z, v.w, h1, l1);
    uint2 ho = {h0, h1}, loo = {l0, l1};
    hi[i] = ho; lo[i] = loo;
}

// ---------------- mma.sync bf16-split GEMM ----------------------------------
#define BK 32
#define NCHUNK (EMB/BK)            // 32
#define ROW_B 80
#define TILE_BYT (128*ROW_B)       // 10240
#define STAGE_BYT (4*TILE_BYT)     // 40960
#define GEMM_SMEM (2*STAGE_BYT)    // 81920

__global__ __launch_bounds__(256) void gemm_mma(
    const __nv_bfloat16* __restrict__ Ahi, const __nv_bfloat16* __restrict__ Alo,
    const __nv_bfloat16* __restrict__ Bhi, const __nv_bfloat16* __restrict__ Blo,
    const float* __restrict__ bias, float scale,
    float* __restrict__ Cf,
    __nv_bfloat16* __restrict__ Chi, __nv_bfloat16* __restrict__ Clo)
{
    extern __shared__ char smc[];
    const int tid = threadIdx.x;
    const int lane = tid & 31, w = tid >> 5;
    const int wy = w >> 2, wx = w & 3;
    const int bx = blockIdx.x * 128, by = blockIdx.y * 128;
    const uint32_t sbase = smem_u32(smc);

    const char* gsrc[4] = {
        (const char*)(Ahi + (size_t)by * EMB),
        (const char*)(Alo + (size_t)by * EMB),
        (const char*)(Bhi + (size_t)bx * EMB),
        (const char*)(Blo + (size_t)bx * EMB)};

    auto prefetch = [&](int kb, int st) {
#pragma unroll
        for (int t = 0; t < 4; t++)
#pragma unroll
            for (int s = 0; s < 2; s++) {
                int idx = tid + s * 256;
                int r = idx >> 2, c = idx & 3;
                const char* src = gsrc[t] + ((size_t)r * EMB + (size_t)kb * BK) * 2 + c * 16;
                uint32_t dst = sbase + (uint32_t)st * STAGE_BYT + t * TILE_BYT
                             + (uint32_t)r * ROW_B + c * 16;
                asm volatile("cp.async.cg.shared.global [%0], [%1], 16;"
                             :: "r"(dst), "l"(src));
            }
        asm volatile("cp.async.commit_group;");
    };

    float acc[4][4][4];
#pragma unroll
    for (int mi = 0; mi < 4; mi++)
#pragma unroll
        for (int ni = 0; ni < 4; ni++)
#pragma unroll
            for (int j = 0; j < 4; j++) acc[mi][ni][j] = 0.f;

    prefetch(0, 0);

    for (int kb = 0; kb < NCHUNK; kb++) {
        if (kb + 1 < NCHUNK) {
            prefetch(kb + 1, (kb + 1) & 1);
            asm volatile("cp.async.wait_group 1;");
        } else {
            asm volatile("cp.async.wait_group 0;");
        }
        __syncthreads();
        const uint32_t st = sbase + (uint32_t)(kb & 1) * STAGE_BYT;

#pragma unroll
        for (int ks = 0; ks < 2; ks++) {
            uint32_t bh[4][2], bl[4][2];
            const uint32_t brow = wx * 32 + (lane & 7);
            const uint32_t bcol = ks * 16 + ((lane >> 3) & 1) * 8;
#pragma unroll
            for (int ni = 0; ni < 4; ni++) {
                uint32_t ab = st + 2 * TILE_BYT + (brow + ni * 8) * ROW_B + bcol * 2;
                asm volatile("ldmatrix.sync.aligned.m8n8.x2.shared.b16 {%0,%1}, [%2];"
                             : "=r"(bh[ni][0]), "=r"(bh[ni][1]) : "r"(ab));
                uint32_t ab2 = ab + TILE_BYT;
                asm volatile("ldmatrix.sync.aligned.m8n8.x2.shared.b16 {%0,%1}, [%2];"
                             : "=r"(bl[ni][0]), "=r"(bl[ni][1]) : "r"(ab2));
            }
            const uint32_t arow = wy * 64 + (lane & 15);
            const uint32_t acol = ks * 16 + (lane >> 4) * 8;
#pragma unroll
            for (int mi = 0; mi < 4; mi++) {
                uint32_t ah[4], al[4];
                uint32_t aa = st + (arow + mi * 16) * ROW_B + acol * 2;
                asm volatile("ldmatrix.sync.aligned.m8n8.x4.shared.b16 {%0,%1,%2,%3}, [%4];"
                             : "=r"(ah[0]), "=r"(ah[1]), "=r"(ah[2]), "=r"(ah[3]) : "r"(aa));
                uint32_t aa2 = aa + TILE_BYT;
                asm volatile("ldmatrix.sync.aligned.m8n8.x4.shared.b16 {%0,%1,%2,%3}, [%4];"
                             : "=r"(al[0]), "=r"(al[1]), "=r"(al[2]), "=r"(al[3]) : "r"(aa2));
#pragma unroll
                for (int ni = 0; ni < 4; ni++) {
                    mma16816(acc[mi][ni], ah, bh[ni]);
                    mma16816(acc[mi][ni], ah, bl[ni]);
                    mma16816(acc[mi][ni], al, bh[ni]);
                }
            }
        }
        __syncthreads();
    }

    const int g = lane >> 2, tg = lane & 3;
#pragma unroll
    for (int mi = 0; mi < 4; mi++) {
        int row0 = by + wy * 64 + mi * 16 + g;
#pragma unroll
        for (int ni = 0; ni < 4; ni++) {
            int col = bx + wx * 32 + ni * 8 + tg * 2;
            float b0 = __ldg(bias + col), b1 = __ldg(bias + col + 1);
            float x0 = (acc[mi][ni][0] + b0) * scale;
            float y0 = (acc[mi][ni][1] + b1) * scale;
            float x1 = (acc[mi][ni][2] + b0) * scale;
            float y1 = (acc[mi][ni][3] + b1) * scale;
            if (Cf) {
                float2 o0 = {x0, y0}, o1 = {x1, y1};
                *(float2*)&Cf[(size_t)row0 * EMB + col] = o0;
                *(float2*)&Cf[(size_t)(row0 + 8) * EMB + col] = o1;
            } else {
                uint32_t h0, l0, h1, l1;
                split2(x0, y0, h0, l0);
                split2(x1, y1, h1, l1);
                *(uint32_t*)&Chi[(size_t)row0 * EMB + col] = h0;
                *(uint32_t*)&Clo[(size_t)row0 * EMB + col] = l0;
                *(uint32_t*)&Chi[(size_t)(row0 + 8) * EMB + col] = h1;
                *(uint32_t*)&Clo[(size_t)(row0 + 8) * EMB + col] = l1;
            }
        }
    }
}

// ---------------- HMMA flash attention --------------------------------------
// Rows carry 128B payload (HD=64 bf16) -> stride 144B (== 16 mod 128:
// conflict-free ldmatrix, fixes the R4 out-of-bounds with 80B stride).
#define AT_ROW 144
#define AT_QTILE (128*AT_ROW)      // 18432
#define AT_TILE (64*AT_ROW)        // 9216
#define AT_STAGE (4*AT_TILE)       // 36864
#define ATT_SMEM (2*AT_STAGE)      // 73728  (Q staging reuses stage-0 space)

__global__ __launch_bounds__(256) void attn_mma(
    const __nv_bfloat16* __restrict__ Qh_, const __nv_bfloat16* __restrict__ Ql_,
    const __nv_bfloat16* __restrict__ Kh_, const __nv_bfloat16* __restrict__ Kl_,
    const __nv_bfloat16* __restrict__ Vh_, const __nv_bfloat16* __restrict__ Vl_,
    __nv_bfloat16* __restrict__ Ch_, __nv_bfloat16* __restrict__ Cl_)
{
    extern __shared__ char smc[];
    const uint32_t sbase = smem_u32(smc);
    const int tid = threadIdx.x, lane = tid & 31, w = tid >> 5;
    const int b = blockIdx.z, h = blockIdx.y;
    const int q0 = blockIdx.x * 128;
    const size_t base_e = ((size_t)b * SEQ) * EMB + h * HD;

    // ---- stage Q (hi at 0, lo at +AT_QTILE); consumed into regs below ----
#pragma unroll
    for (int s = 0; s < 8; s++) {
        int idx = tid + s * 256;              // 0..2047
        int t = idx >> 10, rem = idx & 1023;
        int r = rem >> 3, c = rem & 7;
        const char* src = (const char*)((t ? Ql_ : Qh_) + base_e + (size_t)(q0 + r) * EMB) + c * 16;
        uint32_t dst = sbase + t * AT_QTILE + (uint32_t)r * AT_ROW + c * 16;
        asm volatile("cp.async.cg.shared.global [%0], [%1], 16;" :: "r"(dst), "l"(src));
    }
    asm volatile("cp.async.commit_group;");
    asm volatile("cp.async.wait_group 0;");
    __syncthreads();

    // ---- extract Q fragments (A-frags, 4 k-steps, hi & lo) ----
    uint32_t qh[4][4], ql[4][4];
    {
        const uint32_t arow = w * 16 + (lane & 15);
#pragma unroll
        for (int ks = 0; ks < 4; ks++) {
            uint32_t aa = sbase + arow * AT_ROW + (ks * 16 + (lane >> 4) * 8) * 2;
            asm volatile("ldmatrix.sync.aligned.m8n8.x4.shared.b16 {%0,%1,%2,%3}, [%4];"
                : "=r"(qh[ks][0]), "=r"(qh[ks][1]), "=r"(qh[ks][2]), "=r"(qh[ks][3]) : "r"(aa));
            uint32_t aa2 = aa + AT_QTILE;
            asm volatile("ldmatrix.sync.aligned.m8n8.x4.shared.b16 {%0,%1,%2,%3}, [%4];"
                : "=r"(ql[ks][0]), "=r"(ql[ks][1]), "=r"(ql[ks][2]), "=r"(ql[ks][3]) : "r"(aa2));
        }
    }
    __syncthreads();

    const __nv_bfloat16* kvsrc[4] = {Kh_, Kl_, Vh_, Vl_};
    auto prefetch = [&](int kb, int st) {
#pragma unroll
        for (int s = 0; s < 8; s++) {
            int idx = tid + s * 256;          // 0..2047
            int t = idx >> 9, rem = idx & 511;
            int r = rem >> 3, c = rem & 7;
            const char* src = (const char*)(kvsrc[t] + base_e + (size_t)(kb * 64 + r) * EMB) + c * 16;
            uint32_t dst = sbase + (uint32_t)st * AT_STAGE + t * AT_TILE
                         + (uint32_t)r * AT_ROW + c * 16;
            asm volatile("cp.async.cg.shared.global [%0], [%1], 16;" :: "r"(dst), "l"(src));
        }
        asm volatile("cp.async.commit_group;");
    };

    float oacc[8][4];
    float m_i[2] = {-1e30f, -1e30f}, l_i[2] = {0.f, 0.f};
#pragma unroll
    for (int j = 0; j < 8; j++)
#pragma unroll
        for (int c = 0; c < 4; c++) oacc[j][c] = 0.f;

    prefetch(0, 0);

    for (int kb = 0; kb < SEQ/64; kb++) {
        if (kb + 1 < SEQ/64) {
            prefetch(kb + 1, (kb + 1) & 1);
            asm volatile("cp.async.wait_group 1;");
        } else {
            asm volatile("cp.async.wait_group 0;");
        }
        __syncthreads();
        const uint32_t st = sbase + (uint32_t)(kb & 1) * AT_STAGE;

        // ---- S = Q K^T (64 s-cols, 3-term split) ----
        float sacc[8][4];
#pragma unroll
        for (int j = 0; j < 8; j++)
#pragma unroll
            for (int c = 0; c < 4; c++) sacc[j][c] = 0.f;

#pragma unroll
        for (int ks = 0; ks < 4; ks++) {
            const uint32_t bcol = ks * 16 + ((lane >> 3) & 1) * 8;
#pragma unroll
            for (int j = 0; j < 8; j++) {
                uint32_t bh[2], bl[2];
                uint32_t ab = st + (j * 8 + (lane & 7)) * AT_ROW + bcol * 2;
                asm volatile("ldmatrix.sync.aligned.m8n8.x2.shared.b16 {%0,%1}, [%2];"
                             : "=r"(bh[0]), "=r"(bh[1]) : "r"(ab));
                uint32_t ab2 = ab + AT_TILE;
                asm volatile("ldmatrix.sync.aligned.m8n8.x2.shared.b16 {%0,%1}, [%2];"
                             : "=r"(bl[0]), "=r"(bl[1]) : "r"(ab2));
                mma16816(sacc[j], qh[ks], bh);
                mma16816(sacc[j], qh[ks], bl);
                mma16816(sacc[j], ql[ks], bh);
            }
        }

        // ---- online softmax ----
#pragma unroll
        for (int rh = 0; rh < 2; rh++) {
            float mx = -1e30f;
#pragma unroll
            for (int j = 0; j < 8; j++)
                mx = fmaxf(mx, fmaxf(sacc[j][2*rh], sacc[j][2*rh+1]));
            mx = fmaxf(mx, __shfl_xor_sync(0xffffffffu, mx, 1));
            mx = fmaxf(mx, __shfl_xor_sync(0xffffffffu, mx, 2));
            float m_new = fmaxf(m_i[rh], mx);
            float corr = __expf(m_i[rh] - m_new);
            float sum = 0.f;
#pragma unroll
            for (int j = 0; j < 8; j++) {
                float p0 = __expf(sacc[j][2*rh]   - m_new);
                float p1 = __expf(sacc[j][2*rh+1] - m_new);
                sacc[j][2*rh] = p0; sacc[j][2*rh+1] = p1;
                sum += p0 + p1;
            }
            sum += __shfl_xor_sync(0xffffffffu, sum, 1);
            sum += __shfl_xor_sync(0xffffffffu, sum, 2);
            l_i[rh] = l_i[rh] * corr + sum;
            m_i[rh] = m_new;
#pragma unroll
            for (int j = 0; j < 8; j++) {
                oacc[j][2*rh]   *= corr;
                oacc[j][2*rh+1] *= corr;
            }
        }

        // ---- pack P into A-fragments (hi/lo) ----
        uint32_t phi[4][4], plo[4][4];
#pragma unroll
        for (int ks = 0; ks < 4; ks++) {
            split2(sacc[2*ks][0],   sacc[2*ks][1],   phi[ks][0], plo[ks][0]);
            split2(sacc[2*ks][2],   sacc[2*ks][3],   phi[ks][1], plo[ks][1]);
            split2(sacc[2*ks+1][0], sacc[2*ks+1][1], phi[ks][2], plo[ks][2]);
            split2(sacc[2*ks+1][2], sacc[2*ks+1][3], phi[ks][3], plo[ks][3]);
        }

        // ---- O += P V (V via ldmatrix.trans, 3-term split) ----
#pragma unroll
        for (int ks = 0; ks < 4; ks++) {
            const uint32_t vrow = ks * 16 + (lane & 15);
            const uint32_t vsub = (lane >> 4) * 8;
#pragma unroll
            for (int jj = 0; jj < 4; jj++) {
                uint32_t vh[4], vl[4];
                uint32_t va = st + 2 * AT_TILE + vrow * AT_ROW + (jj * 16 + vsub) * 2;
                asm volatile("ldmatrix.sync.aligned.m8n8.x4.trans.shared.b16 {%0,%1,%2,%3}, [%4];"
                    : "=r"(vh[0]), "=r"(vh[1]), "=r"(vh[2]), "=r"(vh[3]) : "r"(va));
                uint32_t va2 = va + AT_TILE;
                asm volatile("ldmatrix.sync.aligned.m8n8.x4.trans.shared.b16 {%0,%1,%2,%3}, [%4];"
                    : "=r"(vl[0]), "=r"(vl[1]), "=r"(vl[2]), "=r"(vl[3]) : "r"(va2));
                mma16816(oacc[2*jj],   phi[ks], &vh[0]);
                mma16816(oacc[2*jj],   phi[ks], &vl[0]);
                mma16816(oacc[2*jj],   plo[ks], &vh[0]);
                mma16816(oacc[2*jj+1], phi[ks], &vh[2]);
                mma16816(oacc[2*jj+1], phi[ks], &vl[2]);
                mma16816(oacc[2*jj+1], plo[ks], &vh[2]);
            }
        }
        __syncthreads();
    }

    // ---- epilogue: normalize, split, store context hi/lo ----
    const int g = lane >> 2, tg = lane & 3;
#pragma unroll
    for (int rh = 0; rh < 2; rh++) {
        float inv = 1.0f / l_i[rh];
        int row = q0 + w * 16 + g + 8 * rh;
        size_t ro = base_e + (size_t)row * EMB;
#pragma unroll
        for (int j = 0; j < 8; j++) {
            int col = j * 8 + tg * 2;
            uint32_t hi, lo;
            split2(oacc[j][2*rh] * inv, oacc[j][2*rh+1] * inv, hi, lo);
            *(uint32_t*)&Ch_[ro + col] = hi;
            *(uint32_t*)&Cl_[ro + col] = lo;
        }
    }
}

// ---------------------------------------------------------------------------
extern "C" void kernel_launch(void* const* d_in, const int* in_sizes, int n_in,
                              void* d_out, int out_size)
{
    const float* q  = (const float*)d_in[0];
    const float* k  = (const float*)d_in[1];
    const float* v  = (const float*)d_in[2];
    const float* Wq = (const float*)d_in[3];
    const float* bq = (const float*)d_in[4];
    const float* Wk = (const float*)d_in[5];
    const float* bk = (const float*)d_in[6];
    const float* Wv = (const float*)d_in[7];
    const float* bv = (const float*)d_in[8];
    const float* Wo = (const float*)d_in[9];
    const float* bo = (const float*)d_in[10];
    float* out = (float*)d_out;

    __nv_bfloat16 *qh, *ql, *kh, *kl, *vh, *vl, *ch, *cl, *inh, *inl, *wh, *wl;
    cudaGetSymbolAddress((void**)&qh, g_Qh);  cudaGetSymbolAddress((void**)&ql, g_Ql);
    cudaGetSymbolAddress((void**)&kh, g_Kh);  cudaGetSymbolAddress((void**)&kl, g_Kl);
    cudaGetSymbolAddress((void**)&vh, g_Vh);  cudaGetSymbolAddress((void**)&vl, g_Vl);
    cudaGetSymbolAddress((void**)&ch, g_Ch);  cudaGetSymbolAddress((void**)&cl, g_Cl);
    cudaGetSymbolAddress((void**)&inh, g_in_hi); cudaGetSymbolAddress((void**)&inl, g_in_lo);
    cudaGetSymbolAddress((void**)&wh, g_w_hi);   cudaGetSymbolAddress((void**)&wl, g_w_lo);

    cudaFuncSetAttribute(gemm_mma,
        cudaFuncAttributeMaxDynamicSharedMemorySize, GEMM_SMEM);
    cudaFuncSetAttribute(attn_mma,
        cudaFuncAttributeMaxDynamicSharedMemorySize, ATT_SMEM);

    const int n4_in = M_TOT * EMB / 4;
    const int n4_w  = EMB * EMB / 4;
    dim3 gg(EMB / 128, M_TOT / 128);     // (8, 64)
    const float scaling = 0.125f;        // 64^-0.5

    // Q projection -> bf16 hi/lo
    split_bf16<<<n4_in/256, 256>>>((const float4*)q, (uint2*)inh, (uint2*)inl, n4_in);
    split_bf16<<<n4_w /256, 256>>>((const float4*)Wq, (uint2*)wh, (uint2*)wl, n4_w);
    gemm_mma<<<gg, 256, GEMM_SMEM>>>(inh, inl, wh, wl, bq, scaling, nullptr, qh, ql);
    // K projection
    split_bf16<<<n4_in/256, 256>>>((const float4*)k, (uint2*)inh, (uint2*)inl, n4_in);
    split_bf16<<<n4_w /256, 256>>>((const float4*)Wk, (uint2*)wh, (uint2*)wl, n4_w);
    gemm_mma<<<gg, 256, GEMM_SMEM>>>(inh, inl, wh, wl, bk, 1.0f, nullptr, kh, kl);
    // V projection
    split_bf16<<<n4_in/256, 256>>>((const float4*)v, (uint2*)inh, (uint2*)inl, n4_in);
    split_bf16<<<n4_w /256, 256>>>((const float4*)Wv, (uint2*)wh, (uint2*)wl, n4_w);
    gemm_mma<<<gg, 256, GEMM_SMEM>>>(inh, inl, wh, wl, bv, 1.0f, nullptr, vh, vl);
    // attention -> context hi/lo
    attn_mma<<<dim3(SEQ/128, NH, BSZ), 256, ATT_SMEM>>>(qh, ql, kh, kl, vh, vl, ch, cl);
    // output projection -> fp32
    split_bf16<<<n4_w /256, 256>>>((const float4*)Wo, (uint2*)wh, (uint2*)wl, n4_w);
    gemm_mma<<<gg, 256, GEMM_SMEM>>>(ch, cl, wh, wl, bo, 1.0f, out, nullptr, nullptr);
}

// round 6
// speedup vs baseline: 2.6537x; 1.0251x over previous
#include <cuda_runtime.h>
#include <cuda_bf16.h>
#include <cstdint>
#include <math.h>

#define BSZ 8
#define SEQ 1024
#define EMB 1024
#define NH 16
#define HD 64
#define M_TOT (BSZ*SEQ)   // 8192
#define MSZ ((size_t)M_TOT*EMB)   // 8388608 elements
#define WSZ ((size_t)EMB*EMB)     // 1048576 elements

// ---------------- scratch (__device__ globals; no allocation allowed) -------
// 3-slot input hi/lo (q,k,v), 4-slot weight hi/lo (Wq,Wk,Wv,Wo),
// 3-slot projected QKV hi/lo, context hi/lo.
__device__ __nv_bfloat16 g_in_hi[3*MSZ];
__device__ __nv_bfloat16 g_in_lo[3*MSZ];
__device__ __nv_bfloat16 g_w_hi[4*WSZ];
__device__ __nv_bfloat16 g_w_lo[4*WSZ];
__device__ __nv_bfloat16 g_P_hi[3*MSZ];
__device__ __nv_bfloat16 g_P_lo[3*MSZ];
__device__ __nv_bfloat16 g_Ch[MSZ];
__device__ __nv_bfloat16 g_Cl[MSZ];

__device__ __forceinline__ uint32_t smem_u32(const void* p) {
    uint32_t a;
    asm("{ .reg .u64 t; cvta.to.shared.u64 t, %1; cvt.u32.u64 %0, t; }"
        : "=r"(a) : "l"(p));
    return a;
}

__device__ __forceinline__ void mma16816(float* c, const uint32_t* a, const uint32_t* b) {
    asm volatile(
        "mma.sync.aligned.m16n8k16.row.col.f32.bf16.bf16.f32 "
        "{%0,%1,%2,%3}, {%4,%5,%6,%7}, {%8,%9}, {%0,%1,%2,%3};"
        : "+f"(c[0]), "+f"(c[1]), "+f"(c[2]), "+f"(c[3])
        : "r"(a[0]), "r"(a[1]), "r"(a[2]), "r"(a[3]), "r"(b[0]), "r"(b[1]));
}

__device__ __forceinline__ void split2(float x, float y, uint32_t& hi, uint32_t& lo) {
    __nv_bfloat16 hx = __float2bfloat16(x), hy = __float2bfloat16(y);
    float rx = x - __bfloat162float(hx), ry = y - __bfloat162float(hy);
    __nv_bfloat162 hp = {hx, hy};
    __nv_bfloat162 lp = {__float2bfloat16(rx), __float2bfloat16(ry)};
    hi = *reinterpret_cast<uint32_t*>(&hp);
    lo = *reinterpret_cast<uint32_t*>(&lp);
}

// ---------------- batched fp32 -> bf16 hi/lo split (7 tensors, 1 launch) ----
struct SplitSrc { const float4* p[7]; };

__global__ __launch_bounds__(256) void split_all(
    SplitSrc s, uint2* __restrict__ inh, uint2* __restrict__ inl,
    uint2* __restrict__ wh, uint2* __restrict__ wl)
{
    const int seg = blockIdx.y;
    const int i = blockIdx.x * 256 + threadIdx.x;
    const int n4 = (seg < 3) ? (int)(MSZ/4) : (int)(WSZ/4);
    if (i >= n4) return;
    float4 v = s.p[seg][i];
    uint32_t h0, l0, h1, l1;
    split2(v.x, v.y, h0, l0);
    split2(v.z, v.w, h1, l1);
    uint2 ho = {h0, h1}, loo = {l0, l1};
    if (seg < 3) {
        size_t off = (size_t)seg * (MSZ/4) + i;
        inh[off] = ho; inl[off] = loo;
    } else {
        size_t off = (size_t)(seg-3) * (WSZ/4) + i;
        wh[off] = ho; wl[off] = loo;
    }
}

// ---------------- mma.sync bf16-split GEMM (z-batched) ----------------------
#define BK 32
#define NCHUNK (EMB/BK)            // 32
#define ROW_B 80
#define TILE_BYT (128*ROW_B)       // 10240
#define STAGE_BYT (4*TILE_BYT)     // 40960
#define GEMM_SMEM (2*STAGE_BYT)    // 81920

__global__ __launch_bounds__(256) void gemm_mma(
    const __nv_bfloat16* __restrict__ Abase_h, const __nv_bfloat16* __restrict__ Abase_l,
    const __nv_bfloat16* __restrict__ Wbase_h, const __nv_bfloat16* __restrict__ Wbase_l,
    const float* __restrict__ b0, const float* __restrict__ b1,
    const float* __restrict__ b2, float scale0,
    __nv_bfloat16* __restrict__ Cbase_h, __nv_bfloat16* __restrict__ Cbase_l,
    float* __restrict__ Cf)
{
    extern __shared__ char smc[];
    const int z = blockIdx.z;
    const int tid = threadIdx.x;
    const int lane = tid & 31, w = tid >> 5;
    const int wy = w >> 2, wx = w & 3;
    const int bx = blockIdx.x * 128, by = blockIdx.y * 128;
    const uint32_t sbase = smem_u32(smc);

    const __nv_bfloat16* Ahi = Abase_h + (size_t)z * MSZ;
    const __nv_bfloat16* Alo = Abase_l + (size_t)z * MSZ;
    const __nv_bfloat16* Whi = Wbase_h + (size_t)z * WSZ;
    const __nv_bfloat16* Wlo = Wbase_l + (size_t)z * WSZ;
    const float* bias = (z == 0) ? b0 : ((z == 1) ? b1 : b2);
    const float scale = (z == 0) ? scale0 : 1.0f;

    const char* gsrc[4] = {
        (const char*)(Ahi + (size_t)by * EMB),
        (const char*)(Alo + (size_t)by * EMB),
        (const char*)(Whi + (size_t)bx * EMB),
        (const char*)(Wlo + (size_t)bx * EMB)};

    auto prefetch = [&](int kb, int st) {
#pragma unroll
        for (int t = 0; t < 4; t++)
#pragma unroll
            for (int s = 0; s < 2; s++) {
                int idx = tid + s * 256;
                int r = idx >> 2, c = idx & 3;
                const char* src = gsrc[t] + ((size_t)r * EMB + (size_t)kb * BK) * 2 + c * 16;
                uint32_t dst = sbase + (uint32_t)st * STAGE_BYT + t * TILE_BYT
                             + (uint32_t)r * ROW_B + c * 16;
                asm volatile("cp.async.cg.shared.global [%0], [%1], 16;"
                             :: "r"(dst), "l"(src));
            }
        asm volatile("cp.async.commit_group;");
    };

    float acc[4][4][4];
#pragma unroll
    for (int mi = 0; mi < 4; mi++)
#pragma unroll
        for (int ni = 0; ni < 4; ni++)
#pragma unroll
            for (int j = 0; j < 4; j++) acc[mi][ni][j] = 0.f;

    prefetch(0, 0);

    for (int kb = 0; kb < NCHUNK; kb++) {
        asm volatile("cp.async.wait_group 0;");
        __syncthreads();   // all warps done with compute(kb-1); stage kb landed
        if (kb + 1 < NCHUNK) prefetch(kb + 1, (kb + 1) & 1);
        const uint32_t st = sbase + (uint32_t)(kb & 1) * STAGE_BYT;

#pragma unroll
        for (int ks = 0; ks < 2; ks++) {
            uint32_t bh[4][2], bl[4][2];
            const uint32_t brow = wx * 32 + (lane & 7);
            const uint32_t bcol = ks * 16 + ((lane >> 3) & 1) * 8;
#pragma unroll
            for (int ni = 0; ni < 4; ni++) {
                uint32_t ab = st + 2 * TILE_BYT + (brow + ni * 8) * ROW_B + bcol * 2;
                asm volatile("ldmatrix.sync.aligned.m8n8.x2.shared.b16 {%0,%1}, [%2];"
                             : "=r"(bh[ni][0]), "=r"(bh[ni][1]) : "r"(ab));
                uint32_t ab2 = ab + TILE_BYT;
                asm volatile("ldmatrix.sync.aligned.m8n8.x2.shared.b16 {%0,%1}, [%2];"
                             : "=r"(bl[ni][0]), "=r"(bl[ni][1]) : "r"(ab2));
            }
            const uint32_t arow = wy * 64 + (lane & 15);
            const uint32_t acol = ks * 16 + (lane >> 4) * 8;
#pragma unroll
            for (int mi = 0; mi < 4; mi++) {
                uint32_t ah[4], al[4];
                uint32_t aa = st + (arow + mi * 16) * ROW_B + acol * 2;
                asm volatile("ldmatrix.sync.aligned.m8n8.x4.shared.b16 {%0,%1,%2,%3}, [%4];"
                             : "=r"(ah[0]), "=r"(ah[1]), "=r"(ah[2]), "=r"(ah[3]) : "r"(aa));
                uint32_t aa2 = aa + TILE_BYT;
                asm volatile("ldmatrix.sync.aligned.m8n8.x4.shared.b16 {%0,%1,%2,%3}, [%4];"
                             : "=r"(al[0]), "=r"(al[1]), "=r"(al[2]), "=r"(al[3]) : "r"(aa2));
#pragma unroll
                for (int ni = 0; ni < 4; ni++) {
                    mma16816(acc[mi][ni], ah, bh[ni]);
                    mma16816(acc[mi][ni], ah, bl[ni]);
                    mma16816(acc[mi][ni], al, bh[ni]);
                }
            }
        }
    }

    __nv_bfloat16* Chi = Cbase_h + (size_t)z * MSZ;
    __nv_bfloat16* Clo = Cbase_l + (size_t)z * MSZ;
    const int g = lane >> 2, tg = lane & 3;
#pragma unroll
    for (int mi = 0; mi < 4; mi++) {
        int row0 = by + wy * 64 + mi * 16 + g;
#pragma unroll
        for (int ni = 0; ni < 4; ni++) {
            int col = bx + wx * 32 + ni * 8 + tg * 2;
            float b0v = __ldg(bias + col), b1v = __ldg(bias + col + 1);
            float x0 = (acc[mi][ni][0] + b0v) * scale;
            float y0 = (acc[mi][ni][1] + b1v) * scale;
            float x1 = (acc[mi][ni][2] + b0v) * scale;
            float y1 = (acc[mi][ni][3] + b1v) * scale;
            if (Cf) {
                float2 o0 = {x0, y0}, o1 = {x1, y1};
                *(float2*)&Cf[(size_t)row0 * EMB + col] = o0;
                *(float2*)&Cf[(size_t)(row0 + 8) * EMB + col] = o1;
            } else {
                uint32_t h0, l0, h1, l1;
                split2(x0, y0, h0, l0);
                split2(x1, y1, h1, l1);
                *(uint32_t*)&Chi[(size_t)row0 * EMB + col] = h0;
                *(uint32_t*)&Clo[(size_t)row0 * EMB + col] = l0;
                *(uint32_t*)&Chi[(size_t)(row0 + 8) * EMB + col] = h1;
                *(uint32_t*)&Clo[(size_t)(row0 + 8) * EMB + col] = l1;
            }
        }
    }
}

// ---------------- HMMA flash attention --------------------------------------
#define AT_ROW 144
#define AT_QTILE (128*AT_ROW)      // 18432
#define AT_TILE (64*AT_ROW)        // 9216
#define AT_STAGE (4*AT_TILE)       // 36864
#define ATT_SMEM (2*AT_STAGE)      // 73728

__global__ __launch_bounds__(256) void attn_mma(
    const __nv_bfloat16* __restrict__ Ph_, const __nv_bfloat16* __restrict__ Pl_,
    __nv_bfloat16* __restrict__ Ch_, __nv_bfloat16* __restrict__ Cl_)
{
    extern __shared__ char smc[];
    const uint32_t sbase = smem_u32(smc);
    const int tid = threadIdx.x, lane = tid & 31, w = tid >> 5;
    const int b = blockIdx.z, h = blockIdx.y;
    const int q0 = blockIdx.x * 128;
    const size_t base_e = ((size_t)b * SEQ) * EMB + h * HD;

    const __nv_bfloat16* Qh_ = Ph_;            // slot 0
    const __nv_bfloat16* Ql_ = Pl_;
    const __nv_bfloat16* Kh_ = Ph_ + MSZ;      // slot 1
    const __nv_bfloat16* Kl_ = Pl_ + MSZ;
    const __nv_bfloat16* Vh_ = Ph_ + 2*MSZ;    // slot 2
    const __nv_bfloat16* Vl_ = Pl_ + 2*MSZ;

    // ---- stage Q (hi at 0, lo at +AT_QTILE); consumed into regs below ----
#pragma unroll
    for (int s = 0; s < 8; s++) {
        int idx = tid + s * 256;
        int t = idx >> 10, rem = idx & 1023;
        int r = rem >> 3, c = rem & 7;
        const char* src = (const char*)((t ? Ql_ : Qh_) + base_e + (size_t)(q0 + r) * EMB) + c * 16;
        uint32_t dst = sbase + t * AT_QTILE + (uint32_t)r * AT_ROW + c * 16;
        asm volatile("cp.async.cg.shared.global [%0], [%1], 16;" :: "r"(dst), "l"(src));
    }
    asm volatile("cp.async.commit_group;");
    asm volatile("cp.async.wait_group 0;");
    __syncthreads();

    uint32_t qh[4][4], ql[4][4];
    {
        const uint32_t arow = w * 16 + (lane & 15);
#pragma unroll
        for (int ks = 0; ks < 4; ks++) {
            uint32_t aa = sbase + arow * AT_ROW + (ks * 16 + (lane >> 4) * 8) * 2;
            asm volatile("ldmatrix.sync.aligned.m8n8.x4.shared.b16 {%0,%1,%2,%3}, [%4];"
                : "=r"(qh[ks][0]), "=r"(qh[ks][1]), "=r"(qh[ks][2]), "=r"(qh[ks][3]) : "r"(aa));
            uint32_t aa2 = aa + AT_QTILE;
            asm volatile("ldmatrix.sync.aligned.m8n8.x4.shared.b16 {%0,%1,%2,%3}, [%4];"
                : "=r"(ql[ks][0]), "=r"(ql[ks][1]), "=r"(ql[ks][2]), "=r"(ql[ks][3]) : "r"(aa2));
        }
    }
    __syncthreads();

    const __nv_bfloat16* kvsrc[4] = {Kh_, Kl_, Vh_, Vl_};
    auto prefetch = [&](int kb, int st) {
#pragma unroll
        for (int s = 0; s < 8; s++) {
            int idx = tid + s * 256;
            int t = idx >> 9, rem = idx & 511;
            int r = rem >> 3, c = rem & 7;
            const char* src = (const char*)(kvsrc[t] + base_e + (size_t)(kb * 64 + r) * EMB) + c * 16;
            uint32_t dst = sbase + (uint32_t)st * AT_STAGE + t * AT_TILE
                         + (uint32_t)r * AT_ROW + c * 16;
            asm volatile("cp.async.cg.shared.global [%0], [%1], 16;" :: "r"(dst), "l"(src));
        }
        asm volatile("cp.async.commit_group;");
    };

    float oacc[8][4];
    float m_i[2] = {-1e30f, -1e30f}, l_i[2] = {0.f, 0.f};
#pragma unroll
    for (int j = 0; j < 8; j++)
#pragma unroll
        for (int c = 0; c < 4; c++) oacc[j][c] = 0.f;

    prefetch(0, 0);

    for (int kb = 0; kb < SEQ/64; kb++) {
        asm volatile("cp.async.wait_group 0;");
        __syncthreads();   // all warps done with compute(kb-1); stage kb landed
        if (kb + 1 < SEQ/64) prefetch(kb + 1, (kb + 1) & 1);
        const uint32_t st = sbase + (uint32_t)(kb & 1) * AT_STAGE;

        // ---- S = Q K^T ----
        float sacc[8][4];
#pragma unroll
        for (int j = 0; j < 8; j++)
#pragma unroll
            for (int c = 0; c < 4; c++) sacc[j][c] = 0.f;

#pragma unroll
        for (int ks = 0; ks < 4; ks++) {
            const uint32_t bcol = ks * 16 + ((lane >> 3) & 1) * 8;
#pragma unroll
            for (int j = 0; j < 8; j++) {
                uint32_t bh[2], bl[2];
                uint32_t ab = st + (j * 8 + (lane & 7)) * AT_ROW + bcol * 2;
                asm volatile("ldmatrix.sync.aligned.m8n8.x2.shared.b16 {%0,%1}, [%2];"
                             : "=r"(bh[0]), "=r"(bh[1]) : "r"(ab));
                uint32_t ab2 = ab + AT_TILE;
                asm volatile("ldmatrix.sync.aligned.m8n8.x2.shared.b16 {%0,%1}, [%2];"
                             : "=r"(bl[0]), "=r"(bl[1]) : "r"(ab2));
                mma16816(sacc[j], qh[ks], bh);
                mma16816(sacc[j], qh[ks], bl);
                mma16816(sacc[j], ql[ks], bh);
            }
        }

        // ---- online softmax ----
#pragma unroll
        for (int rh = 0; rh < 2; rh++) {
            float mx = -1e30f;
#pragma unroll
            for (int j = 0; j < 8; j++)
                mx = fmaxf(mx, fmaxf(sacc[j][2*rh], sacc[j][2*rh+1]));
            mx = fmaxf(mx, __shfl_xor_sync(0xffffffffu, mx, 1));
            mx = fmaxf(mx, __shfl_xor_sync(0xffffffffu, mx, 2));
            float m_new = fmaxf(m_i[rh], mx);
            float corr = __expf(m_i[rh] - m_new);
            float sum = 0.f;
#pragma unroll
            for (int j = 0; j < 8; j++) {
                float p0 = __expf(sacc[j][2*rh]   - m_new);
                float p1 = __expf(sacc[j][2*rh+1] - m_new);
                sacc[j][2*rh] = p0; sacc[j][2*rh+1] = p1;
                sum += p0 + p1;
            }
            sum += __shfl_xor_sync(0xffffffffu, sum, 1);
            sum += __shfl_xor_sync(0xffffffffu, sum, 2);
            l_i[rh] = l_i[rh] * corr + sum;
            m_i[rh] = m_new;
#pragma unroll
            for (int j = 0; j < 8; j++) {
                oacc[j][2*rh]   *= corr;
                oacc[j][2*rh+1] *= corr;
            }
        }

        // ---- pack P into A-fragments (hi/lo) ----
        uint32_t phi[4][4], plo[4][4];
#pragma unroll
        for (int ks = 0; ks < 4; ks++) {
            split2(sacc[2*ks][0],   sacc[2*ks][1],   phi[ks][0], plo[ks][0]);
            split2(sacc[2*ks][2],   sacc[2*ks][3],   phi[ks][1], plo[ks][1]);
            split2(sacc[2*ks+1][0], sacc[2*ks+1][1], phi[ks][2], plo[ks][2]);
            split2(sacc[2*ks+1][2], sacc[2*ks+1][3], phi[ks][3], plo[ks][3]);
        }

        // ---- O += P V ----
#pragma unroll
        for (int ks = 0; ks < 4; ks++) {
            const uint32_t vrow = ks * 16 + (lane & 15);
            const uint32_t vsub = (lane >> 4) * 8;
#pragma unroll
            for (int jj = 0; jj < 4; jj++) {
                uint32_t vh[4], vl[4];
                uint32_t va = st + 2 * AT_TILE + vrow * AT_ROW + (jj * 16 + vsub) * 2;
                asm volatile("ldmatrix.sync.aligned.m8n8.x4.trans.shared.b16 {%0,%1,%2,%3}, [%4];"
                    : "=r"(vh[0]), "=r"(vh[1]), "=r"(vh[2]), "=r"(vh[3]) : "r"(va));
                uint32_t va2 = va + AT_TILE;
                asm volatile("ldmatrix.sync.aligned.m8n8.x4.trans.shared.b16 {%0,%1,%2,%3}, [%4];"
                    : "=r"(vl[0]), "=r"(vl[1]), "=r"(vl[2]), "=r"(vl[3]) : "r"(va2));
                mma16816(oacc[2*jj],   phi[ks], &vh[0]);
                mma16816(oacc[2*jj],   phi[ks], &vl[0]);
                mma16816(oacc[2*jj],   plo[ks], &vh[0]);
                mma16816(oacc[2*jj+1], phi[ks], &vh[2]);
                mma16816(oacc[2*jj+1], phi[ks], &vl[2]);
                mma16816(oacc[2*jj+1], plo[ks], &vh[2]);
            }
        }
    }

    // ---- epilogue ----
    const int g = lane >> 2, tg = lane & 3;
#pragma unroll
    for (int rh = 0; rh < 2; rh++) {
        float inv = 1.0f / l_i[rh];
        int row = q0 + w * 16 + g + 8 * rh;
        size_t ro = base_e + (size_t)row * EMB;
#pragma unroll
        for (int j = 0; j < 8; j++) {
            int col = j * 8 + tg * 2;
            uint32_t hi, lo;
            split2(oacc[j][2*rh] * inv, oacc[j][2*rh+1] * inv, hi, lo);
            *(uint32_t*)&Ch_[ro + col] = hi;
            *(uint32_t*)&Cl_[ro + col] = lo;
        }
    }
}

// ---------------------------------------------------------------------------
extern "C" void kernel_launch(void* const* d_in, const int* in_sizes, int n_in,
                              void* d_out, int out_size)
{
    const float* q  = (const float*)d_in[0];
    const float* k  = (const float*)d_in[1];
    const float* v  = (const float*)d_in[2];
    const float* Wq = (const float*)d_in[3];
    const float* bq = (const float*)d_in[4];
    const float* Wk = (const float*)d_in[5];
    const float* bk = (const float*)d_in[6];
    const float* Wv = (const float*)d_in[7];
    const float* bv = (const float*)d_in[8];
    const float* Wo = (const float*)d_in[9];
    const float* bo = (const float*)d_in[10];
    float* out = (float*)d_out;

    __nv_bfloat16 *inh, *inl, *wh, *wl, *ph, *pl, *ch, *cl;
    cudaGetSymbolAddress((void**)&inh, g_in_hi); cudaGetSymbolAddress((void**)&inl, g_in_lo);
    cudaGetSymbolAddress((void**)&wh, g_w_hi);   cudaGetSymbolAddress((void**)&wl, g_w_lo);
    cudaGetSymbolAddress((void**)&ph, g_P_hi);   cudaGetSymbolAddress((void**)&pl, g_P_lo);
    cudaGetSymbolAddress((void**)&ch, g_Ch);     cudaGetSymbolAddress((void**)&cl, g_Cl);

    cudaFuncSetAttribute(gemm_mma,
        cudaFuncAttributeMaxDynamicSharedMemorySize, GEMM_SMEM);
    cudaFuncSetAttribute(attn_mma,
        cudaFuncAttributeMaxDynamicSharedMemorySize, ATT_SMEM);

    // 1. all 7 splits in one launch
    SplitSrc ss;
    ss.p[0] = (const float4*)q;  ss.p[1] = (const float4*)k;  ss.p[2] = (const float4*)v;
    ss.p[3] = (const float4*)Wq; ss.p[4] = (const float4*)Wk; ss.p[5] = (const float4*)Wv;
    ss.p[6] = (const float4*)Wo;
    split_all<<<dim3((unsigned)(MSZ/4/256), 7), 256>>>(ss, (uint2*)inh, (uint2*)inl,
                                                       (uint2*)wh, (uint2*)wl);

    // 2. merged Q/K/V projections (z = 0,1,2)
    const float scaling = 0.125f;        // 64^-0.5
    gemm_mma<<<dim3(EMB/128, M_TOT/128, 3), 256, GEMM_SMEM>>>(
        inh, inl, wh, wl, bq, bk, bv, scaling, ph, pl, nullptr);

    // 3. attention -> context hi/lo
    attn_mma<<<dim3(SEQ/128, NH, BSZ), 256, ATT_SMEM>>>(ph, pl, ch, cl);

    // 4. output projection -> fp32 (weight slot 3)
    gemm_mma<<<dim3(EMB/128, M_TOT/128, 1), 256, GEMM_SMEM>>>(
        ch, cl, wh + 3*WSZ, wl + 3*WSZ, bo, bo, bo, 1.0f, ch, cl, out);
}